// round 1
// baseline (speedup 1.0000x reference)
#include <cuda_runtime.h>
#include <cstdint>
#include <math.h>

// Problem constants
#define BB 16
#define SS 4096
#define FF 512
#define NC 10
#define HID 64
#define ODIM 128

#define NTHR 256
#define TABSZ 8192
#define TABM  8191
#define HEMPTY 0xFFFFFFFFu   // a NaN bit pattern: cannot occur after canonicalization

// Scratch (static device globals: allowed; no cudaMalloc anywhere)
__device__ int g_perm[BB * SS];
__device__ int g_offs[BB * (NC + 1)];

// ---------------------------------------------------------------------------
// Kernel A: deterministic stable counting sort of y per batch (no atomics).
// Produces g_perm (sample indices grouped by class) and g_offs (segment bounds).
// ---------------------------------------------------------------------------
__global__ void prep_kernel(const int* __restrict__ y) {
    __shared__ int histT[NC][NTHR];   // per-thread per-class counts -> inclusive scan
    __shared__ int curT[NC][NTHR];    // per-thread cursors
    __shared__ int offs[NC + 1];

    const int b = blockIdx.x;
    const int t = threadIdx.x;
    const int* yb = y + b * SS;
    const int base = t * 16;          // contiguous chunk of 16 per thread

#pragma unroll
    for (int c = 0; c < NC; c++) histT[c][t] = 0;
    __syncthreads();

#pragma unroll
    for (int j = 0; j < 16; j++) {
        int c = yb[base + j];
        histT[c][t]++;                // private slot, no race
    }
    __syncthreads();

    // Inclusive Hillis-Steele scan over t for each class
    for (int d = 1; d < NTHR; d <<= 1) {
        int v[NC];
#pragma unroll
        for (int c = 0; c < NC; c++) v[c] = (t >= d) ? histT[c][t - d] : 0;
        __syncthreads();
#pragma unroll
        for (int c = 0; c < NC; c++) histT[c][t] += v[c];
        __syncthreads();
    }

    if (t == 0) {
        offs[0] = 0;
#pragma unroll
        for (int c = 0; c < NC; c++) offs[c + 1] = offs[c] + histT[c][NTHR - 1];
#pragma unroll
        for (int c = 0; c <= NC; c++) g_offs[b * (NC + 1) + c] = offs[c];
    }
    __syncthreads();

#pragma unroll
    for (int c = 0; c < NC; c++)
        curT[c][t] = offs[c] + (t > 0 ? histT[c][t - 1] : 0);
    __syncthreads();

#pragma unroll
    for (int j = 0; j < 16; j++) {
        int s = base + j;
        int c = yb[s];
        int pos = curT[c][t]++;       // private slot, deterministic
        g_perm[b * SS + pos] = s;
    }
}

// ---------------------------------------------------------------------------
// Kernel B: per (b, 4-feature group) CTA: stats + exact unique count + MLP
// ---------------------------------------------------------------------------
// Dynamic smem layout (bytes):
//   [0,      65536)  vals[4][4096] float (canonicalized column values)
//   [65536,  98304)  tab[8192] u32 (hash table)  /  later reused as w2 staging
//   [98304, 100352)  redbuf[64][8] float
//   [100352,100608)  finals[64] float
//   [100608,100656)  soffs[12] int
//   [100656,100752)  statsm[4][6] float
//   [100752,101776)  hs[256] float
//   [101776,101792)  suniq[4] int
#define SMEM_BYTES 101792

__device__ __forceinline__ unsigned hslot(unsigned x) {
    x *= 2654435761u;
    return (x >> 19) & TABM;
}

__global__ void __launch_bounds__(NTHR, 2)
main_kernel(const float* __restrict__ X,
            const float* __restrict__ w1, const float* __restrict__ b1,
            const float* __restrict__ w2, const float* __restrict__ b2,
            float* __restrict__ out) {
    extern __shared__ unsigned char smem[];
    float*    vals   = (float*)(smem);
    unsigned* tab    = (unsigned*)(smem + 65536);
    float*    redbuf = (float*)(smem + 98304);
    float*    finals = (float*)(smem + 100352);
    int*      soffs  = (int*)(smem + 100608);
    float*    statsm = (float*)(smem + 100656);
    float*    hs     = (float*)(smem + 100752);
    int*      suniq  = (int*)(smem + 101776);

    const int t  = threadIdx.x;
    const int fg = blockIdx.x;          // feature group (4 features)
    const int b  = blockIdx.y;
    const int f0 = fg * 4;

    if (t <= NC) soffs[t] = g_offs[b * (NC + 1) + t];
    if (t < 4)  suniq[t] = 0;
    __syncthreads();

    // ----- Phase 1: class-segmented accumulation -----
    // acc layout per feature f (stride 16): 0 sum, 1 sumsq, 2 sumabs, 3 maxabs,
    // 4 nan count, 5..14 per-class sums
    float acc[64];
#pragma unroll
    for (int q = 0; q < 64; q++) acc[q] = 0.f;

    const int*    perm = g_perm + b * SS;
    const float4* Xb   = (const float4*)(X + (size_t)b * SS * FF);

#pragma unroll
    for (int c = 0; c < NC; c++) {
        const int lo = soffs[c], hi = soffs[c + 1];
        for (int i0 = lo; i0 < hi; i0 += NTHR) {
            const int i = i0 + t;
            if (i < hi) {
                const int s = __ldg(&perm[i]);
                const float4 x = __ldg(&Xb[(size_t)s * (FF / 4) + fg]);
                float xv[4] = {x.x, x.y, x.z, x.w};
#pragma unroll
                for (int f = 0; f < 4; f++) {
                    float v = xv[f];
                    const bool isn = (v != v);
                    v = isn ? 0.f : v;
                    const float a = fabsf(v);
                    acc[f * 16 + 0] += v;
                    acc[f * 16 + 1] += v * v;
                    acc[f * 16 + 2] += a;
                    acc[f * 16 + 3]  = fmaxf(acc[f * 16 + 3], a);
                    acc[f * 16 + 4] += isn ? 1.f : 0.f;
                    acc[f * 16 + 5 + c] += v;
                    vals[f * SS + i] = (v == 0.f) ? 0.f : v;   // canonicalize -0
                }
            }
        }
    }
    __syncthreads();

    // ----- Phase 2: block reduction of 64 quantities -----
    const int lane = t & 31, warp = t >> 5;
#pragma unroll
    for (int q = 0; q < 64; q++) {
        float v = acc[q];
        const bool ismax = ((q & 15) == 3);
#pragma unroll
        for (int o = 16; o; o >>= 1) {
            float w = __shfl_xor_sync(0xFFFFFFFFu, v, o);
            v = ismax ? fmaxf(v, w) : (v + w);
        }
        if (lane == 0) redbuf[q * 8 + warp] = v;
    }
    __syncthreads();
    if (t < 64) {
        const bool ismax = ((t & 15) == 3);
        float v = redbuf[t * 8];
#pragma unroll
        for (int w = 1; w < 8; w++)
            v = ismax ? fmaxf(v, redbuf[t * 8 + w]) : (v + redbuf[t * 8 + w]);
        finals[t] = v;
    }

    // ----- Phase 3: exact unique count per feature (atomic-free hashing) -----
    for (int f = 0; f < 4; f++) {
        __syncthreads();
#pragma unroll
        for (int k = 0; k < TABSZ / NTHR; k++) tab[k * NTHR + t] = HEMPTY;
        __syncthreads();

        const float* vf = vals + f * SS;
        // two independent insert machines per thread (ILP halves round count)
        unsigned c0 = __float_as_uint(vf[t]);
        unsigned c1 = __float_as_uint(vf[8 * NTHR + t]);
        unsigned p0 = hslot(c0), p1 = hslot(c1);
        int  n0 = 1, n1 = 9;           // next value index per machine
        bool a0 = true, a1 = true;

        while (__syncthreads_or((int)(a0 | a1))) {   // barrier: prior writes stable
            bool w0 = false, w1 = false;
            if (a0) {
                const unsigned u = tab[p0];
                if (u == c0) {
                    if (n0 < 8) { c0 = __float_as_uint(vf[n0 * NTHR + t]); p0 = hslot(c0); n0++; }
                    else a0 = false;
                } else if (u == HEMPTY) w0 = true;
                else p0 = (p0 + 1) & TABM;
            }
            if (a1) {
                const unsigned u = tab[p1];
                if (u == c1) {
                    if (n1 < 16) { c1 = __float_as_uint(vf[n1 * NTHR + t]); p1 = hslot(c1); n1++; }
                    else a1 = false;
                } else if (u == HEMPTY) w1 = true;
                else p1 = (p1 + 1) & TABM;
            }
            __syncthreads();           // reads done before speculative writes
            if (w0) tab[p0] = c0;
            if (w1) tab[p1] = c1;
        }
        // count occupied slots (== exact distinct count)
        int cnt = 0;
#pragma unroll
        for (int k = 0; k < TABSZ / NTHR; k++) cnt += (tab[k * NTHR + t] != HEMPTY);
#pragma unroll
        for (int o = 16; o; o >>= 1) cnt += __shfl_xor_sync(0xFFFFFFFFu, cnt, o);
        if (lane == 0) atomicAdd(&suniq[f], cnt);
    }
    __syncthreads();

    // ----- Phase 4: assemble 6 stats per feature -----
    if (t < 4) {
        const int f = t;
        const float Sf = (float)SS;
        const float sum    = finals[f * 16 + 0];
        const float sumsq  = finals[f * 16 + 1];
        const float sumabs = finals[f * 16 + 2];
        const float mx     = finals[f * 16 + 3];
        const float nanc   = finals[f * 16 + 4];
        const float g   = sum / Sf;
        const float var = sumsq / Sf - g * g;
        float between = 0.f;
#pragma unroll
        for (int c = 0; c < NC; c++) {
            const float cntc = (float)(soffs[c + 1] - soffs[c]);
            const float cm = finals[f * 16 + 5 + c] / fmaxf(cntc, 1.f);
            const float d = cm - g;
            between += cntc * d * d;
        }
        between /= Sf;
        float st[6];
        st[0] = between / fmaxf(var, 1e-6f);
        st[1] = nanc / Sf;
        st[2] = (float)suniq[f] / Sf;
        st[3] = var;
        st[4] = sumabs / Sf;
        st[5] = mx;
#pragma unroll
        for (int k = 0; k < 6; k++) {
            float v = st[k];
            if (!isfinite(v)) v = 0.f;
            statsm[f * 6 + k] = v;
        }
    }
    __syncthreads();

    // ----- Phase 5: MLP (6 -> 64 -> GELU -> 128) -----
    float* w2s = (float*)tab;          // table is dead; reuse 32KB for w2
#pragma unroll
    for (int k = 0; k < 32; k++) w2s[k * NTHR + t] = __ldg(&w2[k * NTHR + t]);
    {
        const int f = t >> 6, j = t & 63;
        float z = __ldg(&b1[j]);
#pragma unroll
        for (int i = 0; i < 6; i++) z += statsm[f * 6 + i] * __ldg(&w1[i * 64 + j]);
        hs[t] = z * normcdff(z);       // exact GELU: x * Phi(x)
    }
    __syncthreads();

#pragma unroll
    for (int r = 0; r < 2; r++) {
        const int idx = r * NTHR + t;
        const int f = idx >> 7, o = idx & 127;
        float z = __ldg(&b2[o]);
#pragma unroll 8
        for (int j = 0; j < 64; j++) z += hs[f * 64 + j] * w2s[j * 128 + o];
        out[(size_t)(b * FF + f0 + f) * ODIM + o] = z;
    }
}

// ---------------------------------------------------------------------------
extern "C" void kernel_launch(void* const* d_in, const int* in_sizes, int n_in,
                              void* d_out, int out_size) {
    const float* X  = (const float*)d_in[0];
    const int*   y  = (const int*)d_in[1];
    const float* w1 = (const float*)d_in[2];
    const float* b1 = (const float*)d_in[3];
    const float* w2 = (const float*)d_in[4];
    const float* b2 = (const float*)d_in[5];
    float* out = (float*)d_out;

    cudaFuncSetAttribute(main_kernel,
                         cudaFuncAttributeMaxDynamicSharedMemorySize, SMEM_BYTES);

    prep_kernel<<<BB, NTHR>>>(y);
    main_kernel<<<dim3(FF / 4, BB), NTHR, SMEM_BYTES>>>(X, w1, b1, w2, b2, out);
}

// round 2
// speedup vs baseline: 1.1483x; 1.1483x over previous
#include <cuda_runtime.h>
#include <math.h>

#define BB 16
#define SS 4096
#define FF 512
#define NC 10
#define NCH 32
#define CHROWS (SS / NCH)          // 128
#define TABSZ 8192
#define TABM  8191
#define HEMPTY 0xFFFFFFFFu         // NaN pattern; impossible after canonicalization

// global scratch (static device arrays; no allocation)
__device__ int   g_perm[BB * SS];
__device__ int   g_offs[BB * (NC + 1)];
__device__ float g_part[BB * NCH * 15 * FF];   // [b][chunk][q][f]
__device__ int   g_uniq[BB * FF];

__device__ __forceinline__ unsigned hslot(unsigned x) {
    x *= 2654435761u;
    return (x >> 19) & TABM;
}

// ---------------------------------------------------------------------------
// Kernel 1: deterministic stable counting sort of y per batch (atomic-free)
// ---------------------------------------------------------------------------
__global__ void prep_kernel(const int* __restrict__ y) {
    __shared__ int histT[NC][256];
    __shared__ int curT[NC][256];
    __shared__ int offs[NC + 1];

    const int b = blockIdx.x;
    const int t = threadIdx.x;
    const int* yb = y + b * SS;
    const int base = t * 16;

#pragma unroll
    for (int c = 0; c < NC; c++) histT[c][t] = 0;
    __syncthreads();

#pragma unroll
    for (int j = 0; j < 16; j++) histT[yb[base + j]][t]++;
    __syncthreads();

    for (int d = 1; d < 256; d <<= 1) {
        int v[NC];
#pragma unroll
        for (int c = 0; c < NC; c++) v[c] = (t >= d) ? histT[c][t - d] : 0;
        __syncthreads();
#pragma unroll
        for (int c = 0; c < NC; c++) histT[c][t] += v[c];
        __syncthreads();
    }

    if (t == 0) {
        offs[0] = 0;
#pragma unroll
        for (int c = 0; c < NC; c++) offs[c + 1] = offs[c] + histT[c][255];
#pragma unroll
        for (int c = 0; c <= NC; c++) g_offs[b * (NC + 1) + c] = offs[c];
    }
    __syncthreads();

#pragma unroll
    for (int c = 0; c < NC; c++)
        curT[c][t] = offs[c] + (t > 0 ? histT[c][t - 1] : 0);
    __syncthreads();

#pragma unroll
    for (int j = 0; j < 16; j++) {
        int s = base + j;
        int c = yb[s];
        g_perm[b * SS + curT[c][t]++] = s;
    }
}

// ---------------------------------------------------------------------------
// Kernel 2: chunked stats accumulation with fully coalesced row loads.
// Grid (NCH, BB), 128 threads. Thread t owns features [4t, 4t+4).
// Iterates the class-sorted order; class constant per segment -> static index.
// ---------------------------------------------------------------------------
__global__ void __launch_bounds__(128)
stats_kernel(const float* __restrict__ X) {
    __shared__ int soffs[NC + 1];
    __shared__ int sperm[CHROWS];

    const int t  = threadIdx.x;
    const int ck = blockIdx.x, b = blockIdx.y;
    const int cklo = ck * CHROWS, ckhi = cklo + CHROWS;

    if (t <= NC) soffs[t] = g_offs[b * (NC + 1) + t];
    sperm[t] = g_perm[b * SS + cklo + t];
    __syncthreads();

    const float4* Xb = (const float4*)(X + (size_t)b * SS * FF);

    float s0[4] = {0,0,0,0}, s1[4] = {0,0,0,0}, s2[4] = {0,0,0,0};
    float s3[4] = {0,0,0,0}, s4[4] = {0,0,0,0};
    float cls[4][NC];
#pragma unroll
    for (int f = 0; f < 4; f++)
#pragma unroll
        for (int c = 0; c < NC; c++) cls[f][c] = 0.f;

#pragma unroll
    for (int c = 0; c < NC; c++) {
        const int lo = max(cklo, soffs[c]);
        const int hi = min(ckhi, soffs[c + 1]);
        for (int i = lo; i < hi; i++) {
            const int s = sperm[i - cklo];
            const float4 x = __ldg(&Xb[(size_t)s * (FF / 4) + t]);
            float xv[4] = {x.x, x.y, x.z, x.w};
#pragma unroll
            for (int f = 0; f < 4; f++) {
                float v = xv[f];
                const bool isn = (v != v);
                v = isn ? 0.f : v;
                const float a = fabsf(v);
                s0[f] += v;
                s1[f] += v * v;
                s2[f] += a;
                s3[f]  = fmaxf(s3[f], a);
                s4[f] += isn ? 1.f : 0.f;
                cls[f][c] += v;
            }
        }
    }

    float* gp = g_part + (size_t)(b * NCH + ck) * 15 * FF;
#pragma unroll
    for (int f = 0; f < 4; f++) {
        const int fi = t * 4 + f;
        gp[0 * FF + fi] = s0[f];
        gp[1 * FF + fi] = s1[f];
        gp[2 * FF + fi] = s2[f];
        gp[3 * FF + fi] = s3[f];
        gp[4 * FF + fi] = s4[f];
#pragma unroll
        for (int c = 0; c < NC; c++) gp[(5 + c) * FF + fi] = cls[f][c];
    }
}

// ---------------------------------------------------------------------------
// Kernel 3: exact unique count per (b, feature) via atomic-free hashing.
// Grid (FF/4, BB), 512 threads, dyn smem: vals 64KB + table 32KB.
// Per round: full probe SCAN (reads barrier-stable), speculative write at
// EMPTY, re-verify next round. Duplicates move in lockstep -> exact count.
// ---------------------------------------------------------------------------
#define USMEM (65536 + 32768 + 32)

__global__ void __launch_bounds__(512, 2)
uniq_kernel(const float* __restrict__ X) {
    extern __shared__ unsigned char sm[];
    float*    vals = (float*)sm;                  // 4 x 4096 floats
    unsigned* tab  = (unsigned*)(sm + 65536);     // 8192 u32
    int*      scnt = (int*)(sm + 98304);

    const int t  = threadIdx.x;
    const int fg = blockIdx.x, b = blockIdx.y;
    const float4* Xb = (const float4*)(X + (size_t)b * SS * FF);

#pragma unroll
    for (int k = 0; k < 8; k++) {
        const int s = k * 512 + t;
        const float4 x = __ldg(&Xb[(size_t)s * (FF / 4) + fg]);
        float xv[4] = {x.x, x.y, x.z, x.w};
#pragma unroll
        for (int f = 0; f < 4; f++) {
            float v = xv[f];
            v = (v != v) ? 0.f : v;       // NaN -> 0
            v = (v == 0.f) ? 0.f : v;     // -0 -> +0
            vals[f * SS + s] = v;
        }
    }
    if (t < 4) scnt[t] = 0;

    for (int f = 0; f < 4; f++) {
        __syncthreads();                  // vals ready / prior count reads done
#pragma unroll
        for (int k = 0; k < TABSZ / 512; k++) tab[k * 512 + t] = HEMPTY;

        unsigned v[8];
        int p[8];
#pragma unroll
        for (int k = 0; k < 8; k++) {
            v[k] = __float_as_uint(vals[f * SS + k * 512 + t]);
            p[k] = hslot(v[k]);
        }
        __syncthreads();                  // table init visible
#pragma unroll
        for (int k = 0; k < 8; k++) tab[p[k]] = v[k];   // round 0: blind write

        unsigned mask = 0xFFu;
        while (__syncthreads_or((int)mask)) {           // writes now stable
            unsigned wm = 0;
#pragma unroll
            for (int k = 0; k < 8; k++) {
                if (mask & (1u << k)) {
                    int pp = p[k];
                    for (;;) {
                        const unsigned u = tab[pp];
                        if (u == v[k]) { mask &= ~(1u << k); break; }
                        if (u == HEMPTY) { wm |= 1u << k; break; }
                        pp = (pp + 1) & TABM;
                    }
                    p[k] = pp;
                }
            }
            __syncthreads();              // all reads done before writes
#pragma unroll
            for (int k = 0; k < 8; k++)
                if (wm & (1u << k)) tab[p[k]] = v[k];
        }

        int cnt = 0;
#pragma unroll
        for (int k = 0; k < TABSZ / 512; k++) cnt += (tab[k * 512 + t] != HEMPTY);
#pragma unroll
        for (int o = 16; o; o >>= 1) cnt += __shfl_xor_sync(0xFFFFFFFFu, cnt, o);
        if ((t & 31) == 0) atomicAdd(&scnt[f], cnt);
    }
    __syncthreads();
    if (t < 4) g_uniq[b * FF + fg * 4 + t] = scnt[t];
}

// ---------------------------------------------------------------------------
// Kernel 4: reduce chunk partials -> 6 stats -> MLP -> out.
// Grid (4, BB), 256 threads. Dyn smem: sred + sst + hidden(32K) + w2(32K).
// ---------------------------------------------------------------------------
#define MS_RED   0
#define MS_SST   (MS_RED + 15 * 128 * 4)          // 7680
#define MS_H     (MS_SST + 128 * 8 * 4)           // +4096
#define MS_W2    (MS_H + 128 * 64 * 4)            // +32768
#define MS_OFFS  (MS_W2 + 64 * 128 * 4)           // +32768
#define MSMEM    (MS_OFFS + 16 * 4)

__global__ void __launch_bounds__(256)
mlp_kernel(const float* __restrict__ w1, const float* __restrict__ b1,
           const float* __restrict__ w2, const float* __restrict__ b2,
           float* __restrict__ out) {
    extern __shared__ unsigned char sm[];
    float* sred  = (float*)(sm + MS_RED);    // [15][128]
    float* sst   = (float*)(sm + MS_SST);    // [128][8] (6 used)
    float* sh    = (float*)(sm + MS_H);      // [128][64]
    float* sw2   = (float*)(sm + MS_W2);     // [64][128]
    int*   soffs = (int*)(sm + MS_OFFS);

    const int t    = threadIdx.x;
    const int tile = blockIdx.x, b = blockIdx.y;
    const int fl   = t & 127, half = t >> 7;

    if (t <= NC) soffs[t] = g_offs[b * (NC + 1) + t];
    for (int k = t; k < 64 * 128; k += 256) sw2[k] = __ldg(&w2[k]);

    // reduce 32 chunk partials: half 0 -> q 0..7, half 1 -> q 8..14
    const float* gp = g_part + (size_t)(b * NCH) * 15 * FF + tile * 128;
    const int q0 = half ? 8 : 0, q1 = half ? 15 : 8;
    for (int q = q0; q < q1; q++) {
        float acc = 0.f;
        for (int k = 0; k < NCH; k++) {
            const float u = __ldg(&gp[((size_t)k * 15 + q) * FF + fl]);
            acc = (q == 3) ? fmaxf(acc, u) : (acc + u);
        }
        sred[q * 128 + fl] = acc;
    }
    __syncthreads();

    if (half == 0) {
        const float Sf = (float)SS;
        const float sum    = sred[0 * 128 + fl];
        const float sumsq  = sred[1 * 128 + fl];
        const float sumabs = sred[2 * 128 + fl];
        const float mx     = sred[3 * 128 + fl];
        const float nanc   = sred[4 * 128 + fl];
        const float g   = sum / Sf;
        const float var = sumsq / Sf - g * g;
        float between = 0.f;
#pragma unroll
        for (int c = 0; c < NC; c++) {
            const float cntc = (float)(soffs[c + 1] - soffs[c]);
            const float cm = sred[(5 + c) * 128 + fl] / fmaxf(cntc, 1.f);
            const float d = cm - g;
            between += cntc * d * d;
        }
        between /= Sf;
        const int f = tile * 128 + fl;
        float st[6];
        st[0] = between / fmaxf(var, 1e-6f);
        st[1] = nanc / Sf;
        st[2] = (float)g_uniq[b * FF + f] / Sf;
        st[3] = var;
        st[4] = sumabs / Sf;
        st[5] = mx;
#pragma unroll
        for (int k = 0; k < 6; k++) {
            float v = st[k];
            if (!isfinite(v)) v = 0.f;
            sst[fl * 8 + k] = v;
        }
    }
    __syncthreads();

    // hidden layer: 128 features x 64 -> 32 per thread
    for (int k = t; k < 128 * 64; k += 256) {
        const int f = k >> 6, j = k & 63;
        float z = __ldg(&b1[j]);
#pragma unroll
        for (int i = 0; i < 6; i++) z += sst[f * 8 + i] * __ldg(&w1[i * 64 + j]);
        sh[k] = z * normcdff(z);          // exact GELU
    }
    __syncthreads();

    // output: thread (grp=half, o=fl): features grp*64..grp*64+63, output col o
    {
        const int o = fl, grp = half;
        for (int i = 0; i < 64; i++) {
            const int f = grp * 64 + i;
            float z = __ldg(&b2[o]);
#pragma unroll 8
            for (int k = 0; k < 64; k++) z += sh[f * 64 + k] * sw2[k * 128 + o];
            out[((size_t)(b * FF) + tile * 128 + f) * 128 + o] = z;
        }
    }
}

// ---------------------------------------------------------------------------
extern "C" void kernel_launch(void* const* d_in, const int* in_sizes, int n_in,
                              void* d_out, int out_size) {
    const float* X  = (const float*)d_in[0];
    const int*   y  = (const int*)d_in[1];
    const float* w1 = (const float*)d_in[2];
    const float* b1 = (const float*)d_in[3];
    const float* w2 = (const float*)d_in[4];
    const float* b2 = (const float*)d_in[5];
    float* out = (float*)d_out;

    cudaFuncSetAttribute(uniq_kernel,
                         cudaFuncAttributeMaxDynamicSharedMemorySize, USMEM);
    cudaFuncSetAttribute(mlp_kernel,
                         cudaFuncAttributeMaxDynamicSharedMemorySize, MSMEM);

    prep_kernel<<<BB, 256>>>(y);
    stats_kernel<<<dim3(NCH, BB), 128>>>(X);
    uniq_kernel<<<dim3(FF / 4, BB), 512, USMEM>>>(X);
    mlp_kernel<<<dim3(4, BB), 256, MSMEM>>>(w1, b1, w2, b2, out);
}